// round 3
// baseline (speedup 1.0000x reference)
#include <cuda_runtime.h>
#include <cuda_bf16.h>
#include <math.h>

// ---------------- problem constants ----------------
#define TT 16
#define NN 2048
#define MM 2048
#define INDIM 128
#define OUTDIM 128
#define FEAT 256
#define HID 128

// ---------------- scratch (device bss, no allocation) ----------------
__device__ float4 g_XW  [TT*NN*FEAT/4];   // [T,N,256]: x@W1 | x@W2
__device__ float4 g_FEAT[TT*NN*FEAT/4];   // [T,N,256]: h_in | h_out
__device__ float4 g_G   [TT*NN*FEAT/4];   // [T,N,256]
__device__ float4 g_GAT [TT*NN*FEAT/4];   // [T,N,256]
__device__ float4 g_SEQ [TT*MM*FEAT/4];   // [T,M,256]
__device__ float4 g_ZX  [TT*MM*512/4];    // [T,M,512]
__device__ float4 g_S   [TT*NN/4];
__device__ float4 g_D   [TT*NN/4];
__device__ float4 g_RM  [TT*NN/4];
__device__ float4 g_RI  [TT*NN/4];
__device__ float4 g_H   [2*MM*HID/4];
__device__ float4 g_C   [MM*HID/4];
__device__ float4 g_WC  [INDIM*FEAT/4];   // [128,256]: W1 | W2
__device__ int    g_is64;

// ---------------- small helpers ----------------
__device__ __forceinline__ float sigf(float x) { return 1.0f / (1.0f + __expf(-x)); }

__device__ __forceinline__ long long ip_at(const void* p, long long idx, int is64) {
    if (is64) return ((const long long*)p)[idx];
    return (long long)((const int*)p)[idx];
}

// detect int64 vs int32 by checking high 32-bit words of cur_ips (sorted, positive, < 1e5)
__global__ void detect_kernel(const unsigned* __restrict__ cur) {
    int lane = threadIdx.x;                 // 32 threads
    unsigned w = cur[2 * lane + 1];
    unsigned mask = __ballot_sync(0xFFFFFFFFu, w == 0u);
    if (lane == 0) g_is64 = (mask == 0xFFFFFFFFu) ? 1 : 0;
}

// Wc[k][0:128]=W1[k][:], Wc[k][128:256]=W2[k][:]
__global__ void combine_w(const float* __restrict__ W1, const float* __restrict__ W2,
                          float* __restrict__ Wc) {
    int i = blockIdx.x * 256 + threadIdx.x;  // 0..16383
    int k = i >> 7, n = i & 127;
    Wc[k * 256 + n]       = W1[i];
    Wc[k * 256 + 128 + n] = W2[i];
}

// ---------------- generic 128x128x16 SGEMM, register double-buffered ----------------
// C[M,Nc] = A[M,K] @ B  (+ bias per column).  B row-major [K,Nc] or (TRANSB) [Nc,K].
// FUSED_P: A holds adjacency; P = softmax weight computed on the fly from (s,d,rm,ri).
template<bool TRANSB, bool FUSED_P>
__global__ __launch_bounds__(256)
void sgemm128(const float* __restrict__ A, const float* __restrict__ B,
              float* __restrict__ C,
              int M, int Nc, int K, int lda, int ldb, int ldc,
              long sA, long sB, long sC,
              const float* __restrict__ bias,
              const float* __restrict__ sv, const float* __restrict__ dv,
              const float* __restrict__ rm, const float* __restrict__ ri)
{
    const int BM = 128, BN = 128, BK = 16;
    __shared__ __align__(16) float As[BK][BM];
    __shared__ __align__(16) float Bs[BK][BN];
    __shared__ float s_sh[BM], rm_sh[BM], ri_sh[BM], d_sh[BK];

    int t = blockIdx.z;
    A += (long)t * sA; B += (long)t * sB; C += (long)t * sC;
    int bm = blockIdx.x, bn = blockIdx.y;
    int tid = threadIdx.x;

    if (FUSED_P) {
        if (tid < BM) {
            long r = (long)t * NN + bm * BM + tid;
            s_sh[tid]  = sv[r];
            rm_sh[tid] = rm[r];
            ri_sh[tid] = ri[r];
        }
    }

    float acc[8][8];
#pragma unroll
    for (int i = 0; i < 8; i++)
#pragma unroll
        for (int j = 0; j < 8; j++) acc[i][j] = 0.0f;

    int tx = tid & 15, ty = tid >> 4;
    const int row0 = ty * 8, col0 = tx * 8;

    // per-thread load coordinates (2 float4 each for A and B tiles)
    const int ia0 = tid * 2, ia1 = tid * 2 + 1;
    const int am0 = ia0 >> 2, ak0 = (ia0 & 3) * 4;
    const int am1 = ia1 >> 2, ak1 = (ia1 & 3) * 4;
    // B non-trans coords
    const int br0 = ia0 >> 5, bc0 = (ia0 & 31) * 4;
    const int br1 = ia1 >> 5, bc1 = (ia1 & 31) * 4;
    // B trans coords
    const int bn0 = ia0 >> 2, bk0r = (ia0 & 3) * 4;
    const int bn1 = ia1 >> 2, bk1r = (ia1 & 3) * 4;

    float4 pa0, pa1, pb0, pb1;

    // prefetch tile k0 = 0
    pa0 = *(const float4*)(A + (long)(bm * BM + am0) * lda + ak0);
    pa1 = *(const float4*)(A + (long)(bm * BM + am1) * lda + ak1);
    if (TRANSB) {
        pb0 = *(const float4*)(B + (long)(bn * BN + bn0) * ldb + bk0r);
        pb1 = *(const float4*)(B + (long)(bn * BN + bn1) * ldb + bk1r);
    } else {
        pb0 = *(const float4*)(B + (long)br0 * ldb + bn * BN + bc0);
        pb1 = *(const float4*)(B + (long)br1 * ldb + bn * BN + bc1);
    }

    for (int k0 = 0; k0 < K; k0 += BK) {
        // stage current tile into smem
        As[ak0 + 0][am0] = pa0.x; As[ak0 + 1][am0] = pa0.y;
        As[ak0 + 2][am0] = pa0.z; As[ak0 + 3][am0] = pa0.w;
        As[ak1 + 0][am1] = pa1.x; As[ak1 + 1][am1] = pa1.y;
        As[ak1 + 2][am1] = pa1.z; As[ak1 + 3][am1] = pa1.w;
        if (TRANSB) {
            Bs[bk0r + 0][bn0] = pb0.x; Bs[bk0r + 1][bn0] = pb0.y;
            Bs[bk0r + 2][bn0] = pb0.z; Bs[bk0r + 3][bn0] = pb0.w;
            Bs[bk1r + 0][bn1] = pb1.x; Bs[bk1r + 1][bn1] = pb1.y;
            Bs[bk1r + 2][bn1] = pb1.z; Bs[bk1r + 3][bn1] = pb1.w;
        } else {
            *(float4*)&Bs[br0][bc0] = pb0;
            *(float4*)&Bs[br1][bc1] = pb1;
        }
        if (FUSED_P) {
            if (tid < BK) d_sh[tid] = dv[(long)t * NN + k0 + tid];
        }
        __syncthreads();

        if (FUSED_P) {
            // transform As in place: P_ij = exp(masked_lrelu(s_i+d_j) - rowmax_i) / rowsum_i
#pragma unroll
            for (int e = 0; e < 8; e++) {
                int lin = tid * 8 + e;         // 0..2047
                int kk = lin >> 7;
                int m  = lin & 127;
                float a = As[kk][m];
                float x = s_sh[m] + d_sh[kk];
                x = (x >= 0.0f) ? x : 0.2f * x;
                float ee = (a > 0.0f) ? x : -1e9f;
                As[kk][m] = __expf(ee - rm_sh[m]) * ri_sh[m];
            }
            __syncthreads();
        }

        // prefetch next tile while computing this one
        int kn = k0 + BK;
        if (kn < K) {
            pa0 = *(const float4*)(A + (long)(bm * BM + am0) * lda + kn + ak0);
            pa1 = *(const float4*)(A + (long)(bm * BM + am1) * lda + kn + ak1);
            if (TRANSB) {
                pb0 = *(const float4*)(B + (long)(bn * BN + bn0) * ldb + kn + bk0r);
                pb1 = *(const float4*)(B + (long)(bn * BN + bn1) * ldb + kn + bk1r);
            } else {
                pb0 = *(const float4*)(B + (long)(kn + br0) * ldb + bn * BN + bc0);
                pb1 = *(const float4*)(B + (long)(kn + br1) * ldb + bn * BN + bc1);
            }
        }

#pragma unroll
        for (int k = 0; k < BK; k++) {
            float4 a0 = *(const float4*)&As[k][row0];
            float4 a1 = *(const float4*)&As[k][row0 + 4];
            float4 b0 = *(const float4*)&Bs[k][col0];
            float4 b1 = *(const float4*)&Bs[k][col0 + 4];
            float a[8] = {a0.x, a0.y, a0.z, a0.w, a1.x, a1.y, a1.z, a1.w};
            float b[8] = {b0.x, b0.y, b0.z, b0.w, b1.x, b1.y, b1.z, b1.w};
#pragma unroll
            for (int i = 0; i < 8; i++)
#pragma unroll
                for (int j = 0; j < 8; j++)
                    acc[i][j] = fmaf(a[i], b[j], acc[i][j]);
        }
        __syncthreads();
    }

    // epilogue
#pragma unroll
    for (int i = 0; i < 8; i++) {
        long m = bm * BM + row0 + i;
#pragma unroll
        for (int j = 0; j < 8; j += 4) {
            int n = bn * BN + col0 + j;
            float4 v = make_float4(acc[i][j], acc[i][j + 1], acc[i][j + 2], acc[i][j + 3]);
            if (bias) {
                v.x += bias[n]; v.y += bias[n + 1]; v.z += bias[n + 2]; v.w += bias[n + 3];
            }
            *(float4*)(C + m * ldc + n) = v;
        }
    }
}

// ---------------- s = g@a_src, d = g@a_dst (one warp per row) ----------------
__global__ __launch_bounds__(256)
void sd_kernel(const float* __restrict__ g, const float* __restrict__ asrc,
               const float* __restrict__ adst, float* __restrict__ s, float* __restrict__ d)
{
    int w = (blockIdx.x * blockDim.x + threadIdx.x) >> 5;
    int lane = threadIdx.x & 31;
    if (w >= TT * NN) return;
    const float* row = g + (long)w * FEAT;
    float sa = 0.0f, da = 0.0f;
#pragma unroll
    for (int q = 0; q < 8; q++) {
        int idx = lane + 32 * q;
        float v = row[idx];
        sa = fmaf(v, asrc[idx], sa);
        da = fmaf(v, adst[idx], da);
    }
#pragma unroll
    for (int o = 16; o > 0; o >>= 1) {
        sa += __shfl_down_sync(0xFFFFFFFFu, sa, o);
        da += __shfl_down_sync(0xFFFFFFFFu, da, o);
    }
    if (lane == 0) { s[w] = sa; d[w] = da; }
}

// ---------------- softmax row stats (max + 1/sum), one block per (t,i) row ----------------
__global__ __launch_bounds__(256)
void stats_kernel(const float* __restrict__ Al, const float* __restrict__ s,
                  const float* __restrict__ d, float* __restrict__ rmax, float* __restrict__ rinv)
{
    int i = blockIdx.x, t = blockIdx.y;
    int tid = threadIdx.x;
    const float* arow = Al + ((long)t * NN + i) * NN;
    const float* dt = d + (long)t * NN;
    float si = s[(long)t * NN + i];

    float ev[8];
    float mx = -3.4e38f;
#pragma unroll
    for (int r = 0; r < 8; r++) {
        int j = r * 256 + tid;
        float a = arow[j];
        float x = si + dt[j];
        x = (x >= 0.0f) ? x : 0.2f * x;
        float e = (a > 0.0f) ? x : -1e9f;
        ev[r] = e;
        mx = fmaxf(mx, e);
    }
    __shared__ float red[256];
    red[tid] = mx; __syncthreads();
#pragma unroll
    for (int o = 128; o > 0; o >>= 1) {
        if (tid < o) red[tid] = fmaxf(red[tid], red[tid + o]);
        __syncthreads();
    }
    mx = red[0];
    __syncthreads();
    float sum = 0.0f;
#pragma unroll
    for (int r = 0; r < 8; r++) sum += __expf(ev[r] - mx);
    red[tid] = sum; __syncthreads();
#pragma unroll
    for (int o = 128; o > 0; o >>= 1) {
        if (tid < o) red[tid] += red[tid + o];
        __syncthreads();
    }
    if (tid == 0) {
        rmax[(long)t * NN + i] = mx;
        rinv[(long)t * NN + i] = 1.0f / red[0];
    }
}

// ---------------- gather: seqs[t,m,:] = found ? gat[t,pos,:] : 0 (one warp per (t,m)) ----------------
__global__ __launch_bounds__(256)
void gather_kernel(const void* __restrict__ ips, const void* __restrict__ cur,
                   const float* __restrict__ gat, float* __restrict__ seqs)
{
    int w = (blockIdx.x * blockDim.x + threadIdx.x) >> 5;
    int lane = threadIdx.x & 31;
    if (w >= TT * MM) return;
    int t = w >> 11, m = w & 2047;
    int is64 = g_is64;
    long long v = ip_at(cur, m, is64);
    int lo = 0, hi = NN;
    while (lo < hi) {
        int mid = (lo + hi) >> 1;
        long long x = ip_at(ips, (long long)t * NN + mid, is64);
        if (x < v) lo = mid + 1; else hi = mid;
    }
    int pos = (lo > NN - 1) ? (NN - 1) : lo;
    bool found = (ip_at(ips, (long long)t * NN + pos, is64) == v);
    float4* dst = (float4*)(seqs + (long)w * FEAT);
    if (found) {
        const float4* src = (const float4*)(gat + ((long)t * NN + pos) * FEAT);
        dst[lane]      = src[lane];
        dst[lane + 32] = src[lane + 32];
    } else {
        float4 z = make_float4(0.f, 0.f, 0.f, 0.f);
        dst[lane] = z; dst[lane + 32] = z;
    }
}

// ---------------- fused LSTM step: z = zx + h@Whh^T + bih + bhh; gates; c,h update ----------------
__global__ __launch_bounds__(256)
void lstm_step(const float* __restrict__ hin, const float* __restrict__ zx,
               const float* __restrict__ Whh, const float* __restrict__ bih,
               const float* __restrict__ bhh, float* __restrict__ c, float* __restrict__ hout)
{
    const int BM = 16, BK = 16;
    __shared__ __align__(16) float Hs[BK][BM];
    __shared__ __align__(16) float Ws[BK][512];
    int bm = blockIdx.x;           // 128 blocks
    int tid = threadIdx.x;
    int rg = tid >> 6;             // 0..3 -> rows rg*4..+3
    int cg = tid & 63;             // 0..63 -> cols cg*2, cg*2+1 per gate

    float acc[4][8];
#pragma unroll
    for (int r = 0; r < 4; r++)
#pragma unroll
        for (int q = 0; q < 8; q++) acc[r][q] = 0.0f;

    for (int k0 = 0; k0 < HID; k0 += BK) {
        {
            int m = tid >> 4, kk = tid & 15;
            Hs[kk][m] = hin[(bm * BM + m) * HID + k0 + kk];
        }
#pragma unroll
        for (int i = 0; i < 8; i++) {
            int idx = tid * 8 + i;        // 0..2047
            int n  = idx >> 2;            // 0..511
            int kk = (idx & 3) * 4;
            float4 v = *(const float4*)(Whh + n * HID + k0 + kk);
            Ws[kk + 0][n] = v.x; Ws[kk + 1][n] = v.y;
            Ws[kk + 2][n] = v.z; Ws[kk + 3][n] = v.w;
        }
        __syncthreads();
#pragma unroll
        for (int k = 0; k < BK; k++) {
            float a[4], b[8];
#pragma unroll
            for (int r = 0; r < 4; r++) a[r] = Hs[k][rg * 4 + r];
#pragma unroll
            for (int gidx = 0; gidx < 4; gidx++) {
                b[gidx * 2]     = Ws[k][gidx * 128 + cg * 2];
                b[gidx * 2 + 1] = Ws[k][gidx * 128 + cg * 2 + 1];
            }
#pragma unroll
            for (int r = 0; r < 4; r++)
#pragma unroll
                for (int q = 0; q < 8; q++)
                    acc[r][q] = fmaf(a[r], b[q], acc[r][q]);
        }
        __syncthreads();
    }

#pragma unroll
    for (int r = 0; r < 4; r++) {
        int m = bm * BM + rg * 4 + r;
#pragma unroll
        for (int q = 0; q < 2; q++) {
            int n = cg * 2 + q;  // 0..127 within gate
            float zi = acc[r][0 + q] + zx[m * 512 + n]       + bih[n]       + bhh[n];
            float zf = acc[r][2 + q] + zx[m * 512 + 128 + n] + bih[128 + n] + bhh[128 + n];
            float zg = acc[r][4 + q] + zx[m * 512 + 256 + n] + bih[256 + n] + bhh[256 + n];
            float zo = acc[r][6 + q] + zx[m * 512 + 384 + n] + bih[384 + n] + bhh[384 + n];
            float co = c[m * HID + n];
            float cn = sigf(zf) * co + sigf(zi) * tanhf(zg);
            float hn = sigf(zo) * tanhf(cn);
            c[m * HID + n] = cn;
            hout[m * HID + n] = hn;
        }
    }
}

// ---------------- host ----------------
extern "C" void kernel_launch(void* const* d_in, const int* in_sizes, int n_in,
                              void* d_out, int out_size)
{
    const float* x    = (const float*)d_in[0];
    const float* Ain  = (const float*)d_in[1];
    const float* Aout = (const float*)d_in[2];
    const float* Al   = (const float*)d_in[3];
    const void*  ips  = d_in[4];
    const void*  cur  = d_in[5];
    const float* W1   = (const float*)d_in[6];
    const float* b1   = (const float*)d_in[7];
    const float* W2   = (const float*)d_in[8];
    const float* b2   = (const float*)d_in[9];
    const float* Wg   = (const float*)d_in[10];
    const float* asrc = (const float*)d_in[11];
    const float* adst = (const float*)d_in[12];
    const float* Wih  = (const float*)d_in[13];
    const float* Whh  = (const float*)d_in[14];
    const float* bih  = (const float*)d_in[15];
    const float* bhh  = (const float*)d_in[16];
    float* out = (float*)d_out;

    float *XW, *FT, *G, *GAT, *SEQ, *ZX, *S, *D, *RM, *RI, *H, *C, *WC;
    cudaGetSymbolAddress((void**)&XW,  g_XW);
    cudaGetSymbolAddress((void**)&FT,  g_FEAT);
    cudaGetSymbolAddress((void**)&G,   g_G);
    cudaGetSymbolAddress((void**)&GAT, g_GAT);
    cudaGetSymbolAddress((void**)&SEQ, g_SEQ);
    cudaGetSymbolAddress((void**)&ZX,  g_ZX);
    cudaGetSymbolAddress((void**)&S,   g_S);
    cudaGetSymbolAddress((void**)&D,   g_D);
    cudaGetSymbolAddress((void**)&RM,  g_RM);
    cudaGetSymbolAddress((void**)&RI,  g_RI);
    cudaGetSymbolAddress((void**)&H,   g_H);
    cudaGetSymbolAddress((void**)&C,   g_C);
    cudaGetSymbolAddress((void**)&WC,  g_WC);

    const long NN2 = (long)NN * NN;

    // prep
    combine_w<<<64, 256>>>(W1, W2, WC);
    detect_kernel<<<1, 32>>>((const unsigned*)cur);

    // K1: XW = x @ [W1|W2]    [32768,128] @ [128,256]
    sgemm128<false, false><<<dim3(256, 2, 1), 256>>>(
        x, WC, XW, TT * NN, FEAT, INDIM, INDIM, FEAT, FEAT, 0, 0, 0,
        nullptr, nullptr, nullptr, nullptr, nullptr);

    // K2: feat[:,:128] = Ain @ xW1 + b1 ; feat[:,128:] = Aout @ xW2 + b2
    sgemm128<false, false><<<dim3(16, 1, TT), 256>>>(
        Ain, XW, FT, NN, OUTDIM, NN, NN, FEAT, FEAT,
        NN2, (long)NN * FEAT, (long)NN * FEAT, b1, nullptr, nullptr, nullptr, nullptr);
    sgemm128<false, false><<<dim3(16, 1, TT), 256>>>(
        Aout, XW + 128, FT + 128, NN, OUTDIM, NN, NN, FEAT, FEAT,
        NN2, (long)NN * FEAT, (long)NN * FEAT, b2, nullptr, nullptr, nullptr, nullptr);

    // K3: g = feat @ Wg       [32768,256] @ [256,256]
    sgemm128<false, false><<<dim3(256, 2, 1), 256>>>(
        FT, Wg, G, TT * NN, FEAT, FEAT, FEAT, FEAT, FEAT, 0, 0, 0,
        nullptr, nullptr, nullptr, nullptr, nullptr);

    // s, d
    sd_kernel<<<4096, 256>>>(G, asrc, adst, S, D);

    // softmax row stats
    stats_kernel<<<dim3(NN, TT), 256>>>(Al, S, D, RM, RI);

    // K5: gat = softmax(e) @ g, P computed on the fly
    sgemm128<false, true><<<dim3(16, 2, TT), 256>>>(
        Al, G, GAT, NN, FEAT, NN, NN, FEAT, FEAT,
        NN2, (long)NN * FEAT, (long)NN * FEAT, nullptr, S, D, RM, RI);

    // gather per (t, m)
    gather_kernel<<<4096, 256>>>(ips, cur, GAT, SEQ);

    // ZX = seqs @ Wih^T       [32768,256] @ [256,512]
    sgemm128<true, false><<<dim3(256, 4, 1), 256>>>(
        SEQ, Wih, ZX, TT * MM, 512, FEAT, FEAT, FEAT, 512, 0, 0, 0,
        nullptr, nullptr, nullptr, nullptr, nullptr);

    // h0 = c0 = 0
    cudaMemsetAsync(H, 0, (size_t)MM * HID * sizeof(float));
    cudaMemsetAsync(C, 0, (size_t)MM * HID * sizeof(float));

    // 16 sequential LSTM steps (h ping-pong; last step writes d_out)
    for (int t = 0; t < TT; t++) {
        float* hin  = H + (size_t)(t & 1) * MM * HID;
        float* hout = (t == TT - 1) ? out : H + (size_t)((t + 1) & 1) * MM * HID;
        lstm_step<<<128, 256>>>(hin, ZX + (long)t * MM * 512, Whh, bih, bhh, C, hout);
    }
}

// round 10
// speedup vs baseline: 1.0621x; 1.0621x over previous
#include <cuda_runtime.h>
#include <cuda_bf16.h>
#include <math.h>

// ---------------- problem constants ----------------
#define TT 16
#define NN 2048
#define MM 2048
#define INDIM 128
#define OUTDIM 128
#define FEAT 256
#define HID 128

// ---------------- scratch (device bss, no allocation) ----------------
__device__ float4 g_XW  [TT*NN*FEAT/4];   // [T,N,256]: x@W1 | x@W2
__device__ float4 g_FEAT[TT*NN*FEAT/4];   // [T,N,256]: h_in | h_out
__device__ float4 g_G   [TT*NN*FEAT/4];   // [T,N,256]
__device__ float4 g_GAT [TT*NN*FEAT/4];   // [T,N,256]
__device__ float4 g_SEQ [TT*MM*FEAT/4];   // [T,M,256]
__device__ float4 g_ZX  [TT*MM*512/4];    // [T,M,512]
__device__ float4 g_S   [TT*NN/4];
__device__ float4 g_D   [TT*NN/4];
__device__ float4 g_RM  [TT*NN/4];
__device__ float4 g_RI  [TT*NN/4];
__device__ float4 g_WC  [INDIM*FEAT/4];   // [128,256]: W1 | W2
__device__ int    g_is64;

// ---------------- small helpers ----------------
__device__ __forceinline__ float sigf(float x) { return 1.0f / (1.0f + __expf(-x)); }

__device__ __forceinline__ long long ip_at(const void* p, long long idx, int is64) {
    if (is64) return ((const long long*)p)[idx];
    return (long long)((const int*)p)[idx];
}

// detect int64 vs int32 by checking high 32-bit words of cur_ips (sorted, positive, < 1e5)
__global__ void detect_kernel(const unsigned* __restrict__ cur) {
    int lane = threadIdx.x;                 // 32 threads
    unsigned w = cur[2 * lane + 1];
    unsigned mask = __ballot_sync(0xFFFFFFFFu, w == 0u);
    if (lane == 0) g_is64 = (mask == 0xFFFFFFFFu) ? 1 : 0;
}

// Wc[k][0:128]=W1[k][:], Wc[k][128:256]=W2[k][:]
__global__ void combine_w(const float* __restrict__ W1, const float* __restrict__ W2,
                          float* __restrict__ Wc) {
    int i = blockIdx.x * 256 + threadIdx.x;  // 0..16383
    int k = i >> 7, n = i & 127;
    Wc[k * 256 + n]       = W1[i];
    Wc[k * 256 + 128 + n] = W2[i];
}

// ---------------- generic 128x128x16 SGEMM, register double-buffered ----------------
// C[M,Nc] = A[M,K] @ B  (+ bias per column).  B row-major [K,Nc] or (TRANSB) [Nc,K].
// FUSED_P: A holds adjacency; P = softmax weight computed on the fly from (s,d,rm,ri).
// __launch_bounds__(256, 2): cap regs at 128 so 2 CTAs/SM fit (round-3 ncu: 129 regs ->
// 1 CTA/SM, occ 12.5%, issue 63.9% -> latency-bound; second CTA covers sync bubbles).
template<bool TRANSB, bool FUSED_P>
__global__ __launch_bounds__(256, 2)
void sgemm128(const float* __restrict__ A, const float* __restrict__ B,
              float* __restrict__ C,
              int M, int Nc, int K, int lda, int ldb, int ldc,
              long sA, long sB, long sC,
              const float* __restrict__ bias,
              const float* __restrict__ sv, const float* __restrict__ dv,
              const float* __restrict__ rm, const float* __restrict__ ri)
{
    const int BM = 128, BN = 128, BK = 16;
    __shared__ __align__(16) float As[BK][BM];
    __shared__ __align__(16) float Bs[BK][BN];
    __shared__ float s_sh[BM], rm_sh[BM], ri_sh[BM], d_sh[BK];

    int t = blockIdx.z;
    A += (long)t * sA; B += (long)t * sB; C += (long)t * sC;
    int bm = blockIdx.x, bn = blockIdx.y;
    int tid = threadIdx.x;

    if (FUSED_P) {
        if (tid < BM) {
            long r = (long)t * NN + bm * BM + tid;
            s_sh[tid]  = sv[r];
            rm_sh[tid] = rm[r];
            ri_sh[tid] = ri[r];
        }
    }

    float acc[8][8];
#pragma unroll
    for (int i = 0; i < 8; i++)
#pragma unroll
        for (int j = 0; j < 8; j++) acc[i][j] = 0.0f;

    int tx = tid & 15, ty = tid >> 4;
    const int row0 = ty * 8, col0 = tx * 8;

    // per-thread load coordinates (2 float4 each for A and B tiles)
    const int ia0 = tid * 2, ia1 = tid * 2 + 1;
    const int am0 = ia0 >> 2, ak0 = (ia0 & 3) * 4;
    const int am1 = ia1 >> 2, ak1 = (ia1 & 3) * 4;
    // B non-trans coords
    const int br0 = ia0 >> 5, bc0 = (ia0 & 31) * 4;
    const int br1 = ia1 >> 5, bc1 = (ia1 & 31) * 4;
    // B trans coords
    const int bn0 = ia0 >> 2, bk0r = (ia0 & 3) * 4;
    const int bn1 = ia1 >> 2, bk1r = (ia1 & 3) * 4;

    float4 pa0, pa1, pb0, pb1;

    // prefetch tile k0 = 0
    pa0 = *(const float4*)(A + (long)(bm * BM + am0) * lda + ak0);
    pa1 = *(const float4*)(A + (long)(bm * BM + am1) * lda + ak1);
    if (TRANSB) {
        pb0 = *(const float4*)(B + (long)(bn * BN + bn0) * ldb + bk0r);
        pb1 = *(const float4*)(B + (long)(bn * BN + bn1) * ldb + bk1r);
    } else {
        pb0 = *(const float4*)(B + (long)br0 * ldb + bn * BN + bc0);
        pb1 = *(const float4*)(B + (long)br1 * ldb + bn * BN + bc1);
    }

    for (int k0 = 0; k0 < K; k0 += BK) {
        // stage current tile into smem
        As[ak0 + 0][am0] = pa0.x; As[ak0 + 1][am0] = pa0.y;
        As[ak0 + 2][am0] = pa0.z; As[ak0 + 3][am0] = pa0.w;
        As[ak1 + 0][am1] = pa1.x; As[ak1 + 1][am1] = pa1.y;
        As[ak1 + 2][am1] = pa1.z; As[ak1 + 3][am1] = pa1.w;
        if (TRANSB) {
            Bs[bk0r + 0][bn0] = pb0.x; Bs[bk0r + 1][bn0] = pb0.y;
            Bs[bk0r + 2][bn0] = pb0.z; Bs[bk0r + 3][bn0] = pb0.w;
            Bs[bk1r + 0][bn1] = pb1.x; Bs[bk1r + 1][bn1] = pb1.y;
            Bs[bk1r + 2][bn1] = pb1.z; Bs[bk1r + 3][bn1] = pb1.w;
        } else {
            *(float4*)&Bs[br0][bc0] = pb0;
            *(float4*)&Bs[br1][bc1] = pb1;
        }
        if (FUSED_P) {
            if (tid < BK) d_sh[tid] = dv[(long)t * NN + k0 + tid];
        }
        __syncthreads();

        if (FUSED_P) {
            // transform As in place: P_ij = exp(masked_lrelu(s_i+d_j) - rowmax_i) / rowsum_i
#pragma unroll
            for (int e = 0; e < 8; e++) {
                int lin = tid * 8 + e;         // 0..2047
                int kk = lin >> 7;
                int m  = lin & 127;
                float a = As[kk][m];
                float x = s_sh[m] + d_sh[kk];
                x = (x >= 0.0f) ? x : 0.2f * x;
                float ee = (a > 0.0f) ? x : -1e9f;
                As[kk][m] = __expf(ee - rm_sh[m]) * ri_sh[m];
            }
            __syncthreads();
        }

        // prefetch next tile while computing this one
        int kn = k0 + BK;
        if (kn < K) {
            pa0 = *(const float4*)(A + (long)(bm * BM + am0) * lda + kn + ak0);
            pa1 = *(const float4*)(A + (long)(bm * BM + am1) * lda + kn + ak1);
            if (TRANSB) {
                pb0 = *(const float4*)(B + (long)(bn * BN + bn0) * ldb + kn + bk0r);
                pb1 = *(const float4*)(B + (long)(bn * BN + bn1) * ldb + kn + bk1r);
            } else {
                pb0 = *(const float4*)(B + (long)(kn + br0) * ldb + bn * BN + bc0);
                pb1 = *(const float4*)(B + (long)(kn + br1) * ldb + bn * BN + bc1);
            }
        }

#pragma unroll
        for (int k = 0; k < BK; k++) {
            float4 a0 = *(const float4*)&As[k][row0];
            float4 a1 = *(const float4*)&As[k][row0 + 4];
            float4 b0 = *(const float4*)&Bs[k][col0];
            float4 b1 = *(const float4*)&Bs[k][col0 + 4];
            float a[8] = {a0.x, a0.y, a0.z, a0.w, a1.x, a1.y, a1.z, a1.w};
            float b[8] = {b0.x, b0.y, b0.z, b0.w, b1.x, b1.y, b1.z, b1.w};
#pragma unroll
            for (int i = 0; i < 8; i++)
#pragma unroll
                for (int j = 0; j < 8; j++)
                    acc[i][j] = fmaf(a[i], b[j], acc[i][j]);
        }
        __syncthreads();
    }

    // epilogue
#pragma unroll
    for (int i = 0; i < 8; i++) {
        long m = bm * BM + row0 + i;
#pragma unroll
        for (int j = 0; j < 8; j += 4) {
            int n = bn * BN + col0 + j;
            float4 v = make_float4(acc[i][j], acc[i][j + 1], acc[i][j + 2], acc[i][j + 3]);
            if (bias) {
                v.x += bias[n]; v.y += bias[n + 1]; v.z += bias[n + 2]; v.w += bias[n + 3];
            }
            *(float4*)(C + m * ldc + n) = v;
        }
    }
}

// ---------------- s = g@a_src, d = g@a_dst (one warp per row) ----------------
__global__ __launch_bounds__(256)
void sd_kernel(const float* __restrict__ g, const float* __restrict__ asrc,
               const float* __restrict__ adst, float* __restrict__ s, float* __restrict__ d)
{
    int w = (blockIdx.x * blockDim.x + threadIdx.x) >> 5;
    int lane = threadIdx.x & 31;
    if (w >= TT * NN) return;
    const float* row = g + (long)w * FEAT;
    float sa = 0.0f, da = 0.0f;
#pragma unroll
    for (int q = 0; q < 8; q++) {
        int idx = lane + 32 * q;
        float v = row[idx];
        sa = fmaf(v, asrc[idx], sa);
        da = fmaf(v, adst[idx], da);
    }
#pragma unroll
    for (int o = 16; o > 0; o >>= 1) {
        sa += __shfl_down_sync(0xFFFFFFFFu, sa, o);
        da += __shfl_down_sync(0xFFFFFFFFu, da, o);
    }
    if (lane == 0) { s[w] = sa; d[w] = da; }
}

// ---------------- softmax row stats (max + 1/sum), one block per (t,i) row ----------------
__global__ __launch_bounds__(256)
void stats_kernel(const float* __restrict__ Al, const float* __restrict__ s,
                  const float* __restrict__ d, float* __restrict__ rmax, float* __restrict__ rinv)
{
    int i = blockIdx.x, t = blockIdx.y;
    int tid = threadIdx.x;
    const float* arow = Al + ((long)t * NN + i) * NN;
    const float* dt = d + (long)t * NN;
    float si = s[(long)t * NN + i];

    float ev[8];
    float mx = -3.4e38f;
#pragma unroll
    for (int r = 0; r < 8; r++) {
        int j = r * 256 + tid;
        float a = arow[j];
        float x = si + dt[j];
        x = (x >= 0.0f) ? x : 0.2f * x;
        float e = (a > 0.0f) ? x : -1e9f;
        ev[r] = e;
        mx = fmaxf(mx, e);
    }
    __shared__ float red[256];
    red[tid] = mx; __syncthreads();
#pragma unroll
    for (int o = 128; o > 0; o >>= 1) {
        if (tid < o) red[tid] = fmaxf(red[tid], red[tid + o]);
        __syncthreads();
    }
    mx = red[0];
    __syncthreads();
    float sum = 0.0f;
#pragma unroll
    for (int r = 0; r < 8; r++) sum += __expf(ev[r] - mx);
    red[tid] = sum; __syncthreads();
#pragma unroll
    for (int o = 128; o > 0; o >>= 1) {
        if (tid < o) red[tid] += red[tid + o];
        __syncthreads();
    }
    if (tid == 0) {
        rmax[(long)t * NN + i] = mx;
        rinv[(long)t * NN + i] = 1.0f / red[0];
    }
}

// ---------------- gather: seqs[t,m,:] = found ? gat[t,pos,:] : 0 (one warp per (t,m)) ----------------
__global__ __launch_bounds__(256)
void gather_kernel(const void* __restrict__ ips, const void* __restrict__ cur,
                   const float* __restrict__ gat, float* __restrict__ seqs)
{
    int w = (blockIdx.x * blockDim.x + threadIdx.x) >> 5;
    int lane = threadIdx.x & 31;
    if (w >= TT * MM) return;
    int t = w >> 11, m = w & 2047;
    int is64 = g_is64;
    long long v = ip_at(cur, m, is64);
    int lo = 0, hi = NN;
    while (lo < hi) {
        int mid = (lo + hi) >> 1;
        long long x = ip_at(ips, (long long)t * NN + mid, is64);
        if (x < v) lo = mid + 1; else hi = mid;
    }
    int pos = (lo > NN - 1) ? (NN - 1) : lo;
    bool found = (ip_at(ips, (long long)t * NN + pos, is64) == v);
    float4* dst = (float4*)(seqs + (long)w * FEAT);
    if (found) {
        const float4* src = (const float4*)(gat + ((long)t * NN + pos) * FEAT);
        dst[lane]      = src[lane];
        dst[lane + 32] = src[lane + 32];
    } else {
        float4 z = make_float4(0.f, 0.f, 0.f, 0.f);
        dst[lane] = z; dst[lane + 32] = z;
    }
}

// ---------------- fused persistent LSTM: all 16 steps in one kernel ----------------
// The recurrence is row-independent (z_m depends only on h_m), so each CTA owns 16 rows
// and iterates t=0..15 privately: h in smem (stride 129 kills the stride-128 bank clash),
// c in registers. Identical fmaf ordering to the per-step kernel -> bitwise-same output.
__global__ __launch_bounds__(256)
void lstm_fused(const float* __restrict__ zx0, const float* __restrict__ Whh,
                const float* __restrict__ bih, const float* __restrict__ bhh,
                float* __restrict__ out)
{
    const int BK = 16;
    __shared__ __align__(16) float Hcur[16 * 129];    // h rows (local), padded
    __shared__ __align__(16) float Ws[BK][512];
    int bm = blockIdx.x;           // 128 blocks x 16 rows
    int tid = threadIdx.x;
    int rg = tid >> 6;             // 0..3 -> local rows rg*4..+3
    int cg = tid & 63;             // 0..63 -> cols cg*2, cg*2+1 per gate

    // h0 = 0, c0 = 0
    for (int i = tid; i < 16 * 129; i += 256) Hcur[i] = 0.0f;
    float creg[4][2];
#pragma unroll
    for (int r = 0; r < 4; r++) { creg[r][0] = 0.0f; creg[r][1] = 0.0f; }
    __syncthreads();

    for (int t = 0; t < TT; t++) {
        const float* zx = zx0 + (long)t * MM * 512;

        float acc[4][8];
#pragma unroll
        for (int r = 0; r < 4; r++)
#pragma unroll
            for (int q = 0; q < 8; q++) acc[r][q] = 0.0f;

        for (int k0 = 0; k0 < HID; k0 += BK) {
#pragma unroll
            for (int i = 0; i < 8; i++) {
                int idx = tid * 8 + i;        // 0..2047
                int n  = idx >> 2;            // 0..511
                int kk = (idx & 3) * 4;
                float4 v = *(const float4*)(Whh + n * HID + k0 + kk);
                Ws[kk + 0][n] = v.x; Ws[kk + 1][n] = v.y;
                Ws[kk + 2][n] = v.z; Ws[kk + 3][n] = v.w;
            }
            __syncthreads();
#pragma unroll
            for (int k = 0; k < BK; k++) {
                float a[4], b[8];
#pragma unroll
                for (int r = 0; r < 4; r++) a[r] = Hcur[(rg * 4 + r) * 129 + k0 + k];
#pragma unroll
                for (int gidx = 0; gidx < 4; gidx++) {
                    b[gidx * 2]     = Ws[k][gidx * 128 + cg * 2];
                    b[gidx * 2 + 1] = Ws[k][gidx * 128 + cg * 2 + 1];
                }
#pragma unroll
                for (int r = 0; r < 4; r++)
#pragma unroll
                    for (int q = 0; q < 8; q++)
                        acc[r][q] = fmaf(a[r], b[q], acc[r][q]);
            }
            __syncthreads();
        }

        // gates + state update (same arithmetic/order as the unfused step)
#pragma unroll
        for (int r = 0; r < 4; r++) {
            int ml = rg * 4 + r;               // local row
            int m  = bm * 16 + ml;             // global row
#pragma unroll
            for (int q = 0; q < 2; q++) {
                int n = cg * 2 + q;
                float zi = acc[r][0 + q] + zx[m * 512 + n]       + bih[n]       + bhh[n];
                float zf = acc[r][2 + q] + zx[m * 512 + 128 + n] + bih[128 + n] + bhh[128 + n];
                float zg = acc[r][4 + q] + zx[m * 512 + 256 + n] + bih[256 + n] + bhh[256 + n];
                float zo = acc[r][6 + q] + zx[m * 512 + 384 + n] + bih[384 + n] + bhh[384 + n];
                float co = creg[r][q];
                float cn = sigf(zf) * co + sigf(zi) * tanhf(zg);
                float hn = sigf(zo) * tanhf(cn);
                creg[r][q] = cn;
                if (t == TT - 1) out[m * HID + n] = hn;
                else             Hcur[ml * 129 + n] = hn;
            }
        }
        // Hcur writes are ordered before next step's reads by the __syncthreads
        // following the first Ws staging of the next iteration.
    }
}

// ---------------- host ----------------
extern "C" void kernel_launch(void* const* d_in, const int* in_sizes, int n_in,
                              void* d_out, int out_size)
{
    const float* x    = (const float*)d_in[0];
    const float* Ain  = (const float*)d_in[1];
    const float* Aout = (const float*)d_in[2];
    const float* Al   = (const float*)d_in[3];
    const void*  ips  = d_in[4];
    const void*  cur  = d_in[5];
    const float* W1   = (const float*)d_in[6];
    const float* b1   = (const float*)d_in[7];
    const float* W2   = (const float*)d_in[8];
    const float* b2   = (const float*)d_in[9];
    const float* Wg   = (const float*)d_in[10];
    const float* asrc = (const float*)d_in[11];
    const float* adst = (const float*)d_in[12];
    const float* Wih  = (const float*)d_in[13];
    const float* Whh  = (const float*)d_in[14];
    const float* bih  = (const float*)d_in[15];
    const float* bhh  = (const float*)d_in[16];
    float* out = (float*)d_out;

    float *XW, *FT, *G, *GAT, *SEQ, *ZX, *S, *D, *RM, *RI, *WC;
    cudaGetSymbolAddress((void**)&XW,  g_XW);
    cudaGetSymbolAddress((void**)&FT,  g_FEAT);
    cudaGetSymbolAddress((void**)&G,   g_G);
    cudaGetSymbolAddress((void**)&GAT, g_GAT);
    cudaGetSymbolAddress((void**)&SEQ, g_SEQ);
    cudaGetSymbolAddress((void**)&ZX,  g_ZX);
    cudaGetSymbolAddress((void**)&S,   g_S);
    cudaGetSymbolAddress((void**)&D,   g_D);
    cudaGetSymbolAddress((void**)&RM,  g_RM);
    cudaGetSymbolAddress((void**)&RI,  g_RI);
    cudaGetSymbolAddress((void**)&WC,  g_WC);

    const long NN2 = (long)NN * NN;

    // prep
    combine_w<<<64, 256>>>(W1, W2, WC);
    detect_kernel<<<1, 32>>>((const unsigned*)cur);

    // K1: XW = x @ [W1|W2]    [32768,128] @ [128,256]
    sgemm128<false, false><<<dim3(256, 2, 1), 256>>>(
        x, WC, XW, TT * NN, FEAT, INDIM, INDIM, FEAT, FEAT, 0, 0, 0,
        nullptr, nullptr, nullptr, nullptr, nullptr);

    // K2: feat[:,:128] = Ain @ xW1 + b1 ; feat[:,128:] = Aout @ xW2 + b2
    sgemm128<false, false><<<dim3(16, 1, TT), 256>>>(
        Ain, XW, FT, NN, OUTDIM, NN, NN, FEAT, FEAT,
        NN2, (long)NN * FEAT, (long)NN * FEAT, b1, nullptr, nullptr, nullptr, nullptr);
    sgemm128<false, false><<<dim3(16, 1, TT), 256>>>(
        Aout, XW + 128, FT + 128, NN, OUTDIM, NN, NN, FEAT, FEAT,
        NN2, (long)NN * FEAT, (long)NN * FEAT, b2, nullptr, nullptr, nullptr, nullptr);

    // K3: g = feat @ Wg       [32768,256] @ [256,256]
    sgemm128<false, false><<<dim3(256, 2, 1), 256>>>(
        FT, Wg, G, TT * NN, FEAT, FEAT, FEAT, FEAT, FEAT, 0, 0, 0,
        nullptr, nullptr, nullptr, nullptr, nullptr);

    // s, d + softmax row stats
    sd_kernel<<<4096, 256>>>(G, asrc, adst, S, D);
    stats_kernel<<<dim3(NN, TT), 256>>>(Al, S, D, RM, RI);

    // K5: gat = softmax(e) @ g, P computed on the fly
    sgemm128<false, true><<<dim3(16, 2, TT), 256>>>(
        Al, G, GAT, NN, FEAT, NN, NN, FEAT, FEAT,
        NN2, (long)NN * FEAT, (long)NN * FEAT, nullptr, S, D, RM, RI);

    // gather per (t, m)
    gather_kernel<<<4096, 256>>>(ips, cur, GAT, SEQ);

    // ZX = seqs @ Wih^T       [32768,256] @ [256,512]
    sgemm128<true, false><<<dim3(256, 4, 1), 256>>>(
        SEQ, Wih, ZX, TT * MM, 512, FEAT, FEAT, FEAT, 512, 0, 0, 0,
        nullptr, nullptr, nullptr, nullptr, nullptr);

    // fused 16-step LSTM (h/c CTA-private; writes d_out at t=15)
    lstm_fused<<<128, 256>>>(ZX, Whh, bih, bhh, out);
}

// round 16
// speedup vs baseline: 1.2609x; 1.1872x over previous
#include <cuda_runtime.h>
#include <cuda_bf16.h>
#include <math.h>
#include <stdint.h>

// ---------------- problem constants ----------------
#define TT 16
#define NN 2048
#define MM 2048
#define INDIM 128
#define OUTDIM 128
#define FEAT 256
#define HID 128

// ---------------- scratch (device bss, no allocation) ----------------
__device__ float4 g_XW  [TT*NN*FEAT/4];   // [T,N,256]: x@W1 | x@W2
__device__ float4 g_FEAT[TT*NN*FEAT/4];   // [T,N,256]: h_in | h_out
__device__ float4 g_G   [TT*NN*FEAT/4];   // [T,N,256]
__device__ float4 g_GAT [TT*NN*FEAT/4];   // [T,N,256]
__device__ float4 g_SEQ [TT*MM*FEAT/4];   // [T,M,256]
__device__ float4 g_ZX  [TT*MM*512/4];    // [T,M,512]
__device__ float4 g_S   [TT*NN/4];
__device__ float4 g_D   [TT*NN/4];
__device__ float4 g_V   [TT*NN/4];        // exp(d)
__device__ float4 g_V5  [TT*NN/4];        // exp(0.2 d)
__device__ float4 g_RM  [TT*NN/4];
__device__ float4 g_RI  [TT*NN/4];
__device__ float4 g_WC  [INDIM*FEAT/4];   // [128,256]: W1 | W2
__device__ int    g_is64;

// ---------------- small helpers ----------------
__device__ __forceinline__ float sigf(float x) { return 1.0f / (1.0f + __expf(-x)); }

__device__ __forceinline__ long long ip_at(const void* p, long long idx, int is64) {
    if (is64) return ((const long long*)p)[idx];
    return (long long)((const int*)p)[idx];
}

__device__ __forceinline__ unsigned f2tf32(float f) {
    unsigned u;
    asm("cvt.rna.tf32.f32 %0, %1;" : "=r"(u) : "f"(f));
    return u;
}
// split v into hi (tf32) + lo (tf32 of residual); hi bits reinterpret as exact f32
__device__ __forceinline__ void tf32_split(float v, unsigned& hi, unsigned& lo) {
    hi = f2tf32(v);
    lo = f2tf32(v - __uint_as_float(hi));
}

// m16n8k8 tf32 HMMA (sm_80-era PTX; validated: compiled+ran under harness in R13)
__device__ __forceinline__ void mma_tf32(float* c, const unsigned* a, const unsigned* b) {
    asm volatile(
        "mma.sync.aligned.m16n8k8.row.col.f32.tf32.tf32.f32 "
        "{%0,%1,%2,%3}, {%4,%5,%6,%7}, {%8,%9}, {%0,%1,%2,%3};"
        : "+f"(c[0]), "+f"(c[1]), "+f"(c[2]), "+f"(c[3])
        : "r"(a[0]), "r"(a[1]), "r"(a[2]), "r"(a[3]), "r"(b[0]), "r"(b[1]));
}

// detect int64 vs int32 by checking high 32-bit words of cur_ips
__global__ void detect_kernel(const unsigned* __restrict__ cur) {
    int lane = threadIdx.x;
    unsigned w = cur[2 * lane + 1];
    unsigned mask = __ballot_sync(0xFFFFFFFFu, w == 0u);
    if (lane == 0) g_is64 = (mask == 0xFFFFFFFFu) ? 1 : 0;
}

__global__ void combine_w(const float* __restrict__ W1, const float* __restrict__ W2,
                          float* __restrict__ Wc) {
    int i = blockIdx.x * 256 + threadIdx.x;
    int k = i >> 7, n = i & 127;
    Wc[k * 256 + n]       = W1[i];
    Wc[k * 256 + 128 + n] = W2[i];
}

// column softmax factors: V = exp(d), V5 = exp(0.2 d)
__global__ void vfac_kernel(const float* __restrict__ d, float* __restrict__ V,
                            float* __restrict__ V5) {
    int i = blockIdx.x * 256 + threadIdx.x;   // 0..32767
    float dv = d[i];
    V[i]  = __expf(dv);
    V5[i] = __expf(0.2f * dv);
}

// ---------------- 3xTF32 tensor-core GEMM (HMMA, split-precision) ----------------
// C[128 x 128 tile] = A[.,K] @ B. B row-major [K,Nc] or (TRANSB) [Nc,K].
// Inputs split hi/lo; accumulate a_hi*b_hi + a_hi*b_lo + a_lo*b_hi -> ~f32 accuracy.
// FUSED_P: A = adjacency; P computed on the fly via factored softmax
//   P = (a>0) ? ((s+d>=0) ? u*V[j] : u5*V5[j]) : 0,  u = exp(s-rm)*ri (per row).
template<bool TRANSB, bool FUSED_P>
__global__ __launch_bounds__(256, 2)
void tf32_gemm(const float* __restrict__ A, const float* __restrict__ B,
               float* __restrict__ C, int K, int lda, int ldb, int ldc,
               long sA, long sB, long sC, const float* __restrict__ bias,
               const float* __restrict__ sv, const float* __restrict__ dvec,
               const float* __restrict__ rmv, const float* __restrict__ riv,
               const float* __restrict__ Vv, const float* __restrict__ V5v)
{
    const int PA = 20;    // As row pitch (u32) -> conflict-free fragment loads
    const int PB = 132;   // Bs row pitch (u32)
    __shared__ unsigned As_hi[128 * PA], As_lo[128 * PA];   // [m][k]
    __shared__ unsigned Bs_hi[16 * PB],  Bs_lo[16 * PB];    // [k][n]

    int t = blockIdx.z;
    A += (long)t * sA; B += (long)t * sB; C += (long)t * sC;
    int bm = blockIdx.x, bn = blockIdx.y;
    int tid = threadIdx.x;
    int w = tid >> 5, lane = tid & 31;
    int gq = lane >> 2, tq = lane & 3;
    int mw = (w & 1) * 64, nw = (w >> 1) * 32;

    // staging coordinates
    const int am = tid >> 1;              // A row 0..127
    const int ah = (tid & 1) * 8;         // A k-offset 0/8
    const int bk  = tid >> 4;             // B k-row 0..15 (non-trans)
    const int bn4 = (tid & 15) * 8;       // B n-offset  (non-trans)
    const int bnr = tid >> 1;             // B n-row 0..127 (trans)
    const int bh  = (tid & 1) * 8;        // B k-offset (trans)

    // FUSED_P per-row factors (2 exps per thread total)
    float s_f = 0.0f, u_f = 0.0f, u5_f = 0.0f;
    if (FUSED_P) {
        long r = (long)t * NN + bm * 128 + am;
        s_f = sv[r];
        float rmi = rmv[r], rii = riv[r];
        u_f  = __expf(s_f - rmi) * rii;
        u5_f = __expf(0.2f * s_f - rmi) * rii;
    }

    float acc[4][4][4];
#pragma unroll
    for (int i = 0; i < 4; i++)
#pragma unroll
        for (int j = 0; j < 4; j++)
#pragma unroll
            for (int q = 0; q < 4; q++) acc[i][j][q] = 0.0f;

    for (int k0 = 0; k0 < K; k0 += 16) {
        // ---- stage A (128 x 16), split hi/lo ----
        {
            const float* ar = A + (long)(bm * 128 + am) * lda + k0 + ah;
            float av[8];
            *(float4*)&av[0] = *(const float4*)(ar);
            *(float4*)&av[4] = *(const float4*)(ar + 4);
            if (FUSED_P) {
                long db = (long)t * NN + k0 + ah;
                float dv4[8], vv4[8], wv4[8];
                *(float4*)&dv4[0] = *(const float4*)(dvec + db);
                *(float4*)&dv4[4] = *(const float4*)(dvec + db + 4);
                *(float4*)&vv4[0] = *(const float4*)(Vv + db);
                *(float4*)&vv4[4] = *(const float4*)(Vv + db + 4);
                *(float4*)&wv4[0] = *(const float4*)(V5v + db);
                *(float4*)&wv4[4] = *(const float4*)(V5v + db + 4);
#pragma unroll
                for (int e = 0; e < 8; e++) {
                    float x = s_f + dv4[e];
                    float p = (x >= 0.f) ? u_f * vv4[e] : u5_f * wv4[e];
                    av[e] = (av[e] > 0.f) ? p : 0.0f;
                }
            }
            unsigned* aph = As_hi + am * PA + ah;
            unsigned* apl = As_lo + am * PA + ah;
#pragma unroll
            for (int e = 0; e < 8; e++) {
                unsigned hi, lo;
                tf32_split(av[e], hi, lo);
                aph[e] = hi; apl[e] = lo;
            }
        }
        // ---- stage B (16 x 128, stored k-major Bs[k][n]), split hi/lo ----
        if (TRANSB) {
            const float* br = B + (long)(bn * 128 + bnr) * ldb + k0 + bh;
            float bv[8];
            *(float4*)&bv[0] = *(const float4*)(br);
            *(float4*)&bv[4] = *(const float4*)(br + 4);
#pragma unroll
            for (int e = 0; e < 8; e++) {
                unsigned hi, lo;
                tf32_split(bv[e], hi, lo);
                Bs_hi[(bh + e) * PB + bnr] = hi;
                Bs_lo[(bh + e) * PB + bnr] = lo;
            }
        } else {
            const float* br = B + (long)(k0 + bk) * ldb + bn * 128 + bn4;
            float bv[8];
            *(float4*)&bv[0] = *(const float4*)(br);
            *(float4*)&bv[4] = *(const float4*)(br + 4);
            unsigned* bph = Bs_hi + bk * PB + bn4;
            unsigned* bpl = Bs_lo + bk * PB + bn4;
#pragma unroll
            for (int e = 0; e < 8; e++) {
                unsigned hi, lo;
                tf32_split(bv[e], hi, lo);
                bph[e] = hi; bpl[e] = lo;
            }
        }
        __syncthreads();

        // ---- compute: two k8 steps, 3 HMMA per (mf,nf) fragment pair ----
#pragma unroll
        for (int ks = 0; ks < 2; ks++) {
            int k8 = ks * 8;
            unsigned bfh[4][2], bfl[4][2];
#pragma unroll
            for (int nf = 0; nf < 4; nf++) {
                int n = nw + nf * 8 + gq;
                bfh[nf][0] = Bs_hi[(k8 + tq) * PB + n];
                bfh[nf][1] = Bs_hi[(k8 + tq + 4) * PB + n];
                bfl[nf][0] = Bs_lo[(k8 + tq) * PB + n];
                bfl[nf][1] = Bs_lo[(k8 + tq + 4) * PB + n];
            }
#pragma unroll
            for (int mf = 0; mf < 4; mf++) {
                int r0 = mw + mf * 16 + gq;
                unsigned afh[4], afl[4];
                afh[0] = As_hi[r0 * PA + k8 + tq];
                afh[1] = As_hi[(r0 + 8) * PA + k8 + tq];
                afh[2] = As_hi[r0 * PA + k8 + tq + 4];
                afh[3] = As_hi[(r0 + 8) * PA + k8 + tq + 4];
                afl[0] = As_lo[r0 * PA + k8 + tq];
                afl[1] = As_lo[(r0 + 8) * PA + k8 + tq];
                afl[2] = As_lo[r0 * PA + k8 + tq + 4];
                afl[3] = As_lo[(r0 + 8) * PA + k8 + tq + 4];
#pragma unroll
                for (int nf = 0; nf < 4; nf++) {
                    mma_tf32(acc[mf][nf], afh, bfh[nf]);
                    mma_tf32(acc[mf][nf], afh, bfl[nf]);
                    mma_tf32(acc[mf][nf], afl, bfh[nf]);
                }
            }
        }
        __syncthreads();
    }

    // ---- epilogue: fragment scatter (+bias) ----
#pragma unroll
    for (int mf = 0; mf < 4; mf++) {
        long m0 = (long)bm * 128 + mw + mf * 16 + gq;
#pragma unroll
        for (int nf = 0; nf < 4; nf++) {
            int n = bn * 128 + nw + nf * 8 + 2 * tq;
            float b0v = bias ? bias[n] : 0.0f;
            float b1v = bias ? bias[n + 1] : 0.0f;
            float2 v0 = make_float2(acc[mf][nf][0] + b0v, acc[mf][nf][1] + b1v);
            float2 v1 = make_float2(acc[mf][nf][2] + b0v, acc[mf][nf][3] + b1v);
            *(float2*)(C + m0 * ldc + n) = v0;
            *(float2*)(C + (m0 + 8) * ldc + n) = v1;
        }
    }
}

// ---------------- 128x128x16 SIMT SGEMM (K1, K3 only) ----------------
template<bool TRANSB>
__global__ __launch_bounds__(256, 2)
void sgemm128(const float* __restrict__ A, const float* __restrict__ B,
              float* __restrict__ C,
              int K, int lda, int ldb, int ldc,
              const float* __restrict__ bias)
{
    const int BM = 128, BN = 128, BK = 16;
    __shared__ __align__(16) float As[BK][BM];
    __shared__ __align__(16) float Bs[BK][BN];

    int bm = blockIdx.x, bn = blockIdx.y;
    int tid = threadIdx.x;

    float acc[8][8];
#pragma unroll
    for (int i = 0; i < 8; i++)
#pragma unroll
        for (int j = 0; j < 8; j++) acc[i][j] = 0.0f;

    int tx = tid & 15, ty = tid >> 4;
    const int row0 = ty * 8, col0 = tx * 8;

    const int ia0 = tid * 2, ia1 = tid * 2 + 1;
    const int am0 = ia0 >> 2, ak0 = (ia0 & 3) * 4;
    const int am1 = ia1 >> 2, ak1 = (ia1 & 3) * 4;
    const int br0 = ia0 >> 5, bc0 = (ia0 & 31) * 4;
    const int br1 = ia1 >> 5, bc1 = (ia1 & 31) * 4;
    const int bn0 = ia0 >> 2, bk0r = (ia0 & 3) * 4;
    const int bn1 = ia1 >> 2, bk1r = (ia1 & 3) * 4;

    float4 pa0, pa1, pb0, pb1;
    pa0 = *(const float4*)(A + (long)(bm * BM + am0) * lda + ak0);
    pa1 = *(const float4*)(A + (long)(bm * BM + am1) * lda + ak1);
    if (TRANSB) {
        pb0 = *(const float4*)(B + (long)(bn * BN + bn0) * ldb + bk0r);
        pb1 = *(const float4*)(B + (long)(bn * BN + bn1) * ldb + bk1r);
    } else {
        pb0 = *(const float4*)(B + (long)br0 * ldb + bn * BN + bc0);
        pb1 = *(const float4*)(B + (long)br1 * ldb + bn * BN + bc1);
    }

    for (int k0 = 0; k0 < K; k0 += BK) {
        As[ak0 + 0][am0] = pa0.x; As[ak0 + 1][am0] = pa0.y;
        As[ak0 + 2][am0] = pa0.z; As[ak0 + 3][am0] = pa0.w;
        As[ak1 + 0][am1] = pa1.x; As[ak1 + 1][am1] = pa1.y;
        As[ak1 + 2][am1] = pa1.z; As[ak1 + 3][am1] = pa1.w;
        if (TRANSB) {
            Bs[bk0r + 0][bn0] = pb0.x; Bs[bk0r + 1][bn0] = pb0.y;
            Bs[bk0r + 2][bn0] = pb0.z; Bs[bk0r + 3][bn0] = pb0.w;
            Bs[bk1r + 0][bn1] = pb1.x; Bs[bk1r + 1][bn1] = pb1.y;
            Bs[bk1r + 2][bn1] = pb1.z; Bs[bk1r + 3][bn1] = pb1.w;
        } else {
            *(float4*)&Bs[br0][bc0] = pb0;
            *(float4*)&Bs[br1][bc1] = pb1;
        }
        __syncthreads();

        int kn = k0 + BK;
        if (kn < K) {
            pa0 = *(const float4*)(A + (long)(bm * BM + am0) * lda + kn + ak0);
            pa1 = *(const float4*)(A + (long)(bm * BM + am1) * lda + kn + ak1);
            if (TRANSB) {
                pb0 = *(const float4*)(B + (long)(bn * BN + bn0) * ldb + kn + bk0r);
                pb1 = *(const float4*)(B + (long)(bn * BN + bn1) * ldb + kn + bk1r);
            } else {
                pb0 = *(const float4*)(B + (long)(kn + br0) * ldb + bn * BN + bc0);
                pb1 = *(const float4*)(B + (long)(kn + br1) * ldb + bn * BN + bc1);
            }
        }

#pragma unroll
        for (int k = 0; k < BK; k++) {
            float4 a0 = *(const float4*)&As[k][row0];
            float4 a1 = *(const float4*)&As[k][row0 + 4];
            float4 b0 = *(const float4*)&Bs[k][col0];
            float4 b1 = *(const float4*)&Bs[k][col0 + 4];
            float a[8] = {a0.x, a0.y, a0.z, a0.w, a1.x, a1.y, a1.z, a1.w};
            float b[8] = {b0.x, b0.y, b0.z, b0.w, b1.x, b1.y, b1.z, b1.w};
#pragma unroll
            for (int i = 0; i < 8; i++)
#pragma unroll
                for (int j = 0; j < 8; j++)
                    acc[i][j] = fmaf(a[i], b[j], acc[i][j]);
        }
        __syncthreads();
    }

#pragma unroll
    for (int i = 0; i < 8; i++) {
        long m = bm * BM + row0 + i;
#pragma unroll
        for (int j = 0; j < 8; j += 4) {
            int n = bn * BN + col0 + j;
            float4 v = make_float4(acc[i][j], acc[i][j + 1], acc[i][j + 2], acc[i][j + 3]);
            if (bias) {
                v.x += bias[n]; v.y += bias[n + 1]; v.z += bias[n + 2]; v.w += bias[n + 3];
            }
            *(float4*)(C + m * ldc + n) = v;
        }
    }
}

// ---------------- s = g@a_src, d = g@a_dst ----------------
__global__ __launch_bounds__(256)
void sd_kernel(const float* __restrict__ g, const float* __restrict__ asrc,
               const float* __restrict__ adst, float* __restrict__ s, float* __restrict__ d)
{
    int w = (blockIdx.x * blockDim.x + threadIdx.x) >> 5;
    int lane = threadIdx.x & 31;
    if (w >= TT * NN) return;
    const float* row = g + (long)w * FEAT;
    float sa = 0.0f, da = 0.0f;
#pragma unroll
    for (int q = 0; q < 8; q++) {
        int idx = lane + 32 * q;
        float v = row[idx];
        sa = fmaf(v, asrc[idx], sa);
        da = fmaf(v, adst[idx], da);
    }
#pragma unroll
    for (int o = 16; o > 0; o >>= 1) {
        sa += __shfl_down_sync(0xFFFFFFFFu, sa, o);
        da += __shfl_down_sync(0xFFFFFFFFu, da, o);
    }
    if (lane == 0) { s[w] = sa; d[w] = da; }
}

// ---------------- softmax row stats, exp-factorized (no per-element MUFU) ----------------
__global__ __launch_bounds__(256)
void stats_kernel(const float* __restrict__ Al, const float* __restrict__ s,
                  const float* __restrict__ d, const float* __restrict__ V,
                  const float* __restrict__ V5,
                  float* __restrict__ rmax, float* __restrict__ rinv)
{
    int i = blockIdx.x, t = blockIdx.y;
    int tid = threadIdx.x;
    const float* arow = Al + ((long)t * NN + i) * NN;
    const float* dt  = d  + (long)t * NN;
    const float* Vt  = V  + (long)t * NN;
    const float* V5t = V5 + (long)t * NN;
    float si = s[(long)t * NN + i];

    float dj[8];
    int msk = 0;
    float mx = -3.4e38f;
#pragma unroll
    for (int r = 0; r < 8; r++) {
        int j = r * 256 + tid;
        float a = arow[j];
        float dd = dt[j];
        float x = si + dd;
        float xl = (x >= 0.0f) ? x : 0.2f * x;
        float e = (a > 0.0f) ? xl : -1e9f;
        dj[r] = dd;
        if (a > 0.0f) msk |= (1 << r);
        mx = fmaxf(mx, e);
    }
    __shared__ float red[256];
    red[tid] = mx; __syncthreads();
#pragma unroll
    for (int o = 128; o > 0; o >>= 1) {
        if (tid < o) red[tid] = fmaxf(red[tid], red[tid + o]);
        __syncthreads();
    }
    mx = red[0];
    __syncthreads();

    // sum via factorization: exp(lrelu(s+d)-mx) = (s+d>=0) ? exp(s-mx)V : exp(.2s-mx)V5
    float exS  = __expf(si - mx);
    float exS5 = __expf(0.2f * si - mx);
    float sum = 0.0f;
#pragma unroll
    for (int r = 0; r < 8; r++) {
        int j = r * 256 + tid;
        if (msk & (1 << r)) {
            float x = si + dj[r];
            sum += (x >= 0.0f) ? exS * Vt[j] : exS5 * V5t[j];
        }
    }
    red[tid] = sum; __syncthreads();
#pragma unroll
    for (int o = 128; o > 0; o >>= 1) {
        if (tid < o) red[tid] += red[tid + o];
        __syncthreads();
    }
    if (tid == 0) {
        rmax[(long)t * NN + i] = mx;
        rinv[(long)t * NN + i] = 1.0f / red[0];
    }
}

// ---------------- gather ----------------
__global__ __launch_bounds__(256)
void gather_kernel(const void* __restrict__ ips, const void* __restrict__ cur,
                   const float* __restrict__ gat, float* __restrict__ seqs)
{
    int w = (blockIdx.x * blockDim.x + threadIdx.x) >> 5;
    int lane = threadIdx.x & 31;
    if (w >= TT * MM) return;
    int t = w >> 11, m = w & 2047;
    int is64 = g_is64;
    long long v = ip_at(cur, m, is64);
    int lo = 0, hi = NN;
    while (lo < hi) {
        int mid = (lo + hi) >> 1;
        long long x = ip_at(ips, (long long)t * NN + mid, is64);
        if (x < v) lo = mid + 1; else hi = mid;
    }
    int pos = (lo > NN - 1) ? (NN - 1) : lo;
    bool found = (ip_at(ips, (long long)t * NN + pos, is64) == v);
    float4* dst = (float4*)(seqs + (long)w * FEAT);
    if (found) {
        const float4* src = (const float4*)(gat + ((long)t * NN + pos) * FEAT);
        dst[lane]      = src[lane];
        dst[lane + 32] = src[lane + 32];
    } else {
        float4 z = make_float4(0.f, 0.f, 0.f, 0.f);
        dst[lane] = z; dst[lane + 32] = z;
    }
}

// ---------------- fused persistent LSTM ----------------
__global__ __launch_bounds__(256)
void lstm_fused(const float* __restrict__ zx0, const float* __restrict__ Whh,
                const float* __restrict__ bih, const float* __restrict__ bhh,
                float* __restrict__ out)
{
    const int BK = 16;
    __shared__ __align__(16) float Hcur[16 * 129];
    __shared__ __align__(16) float Ws[BK][512];
    int bm = blockIdx.x;
    int tid = threadIdx.x;
    int rg = tid >> 6;
    int cg = tid & 63;

    for (int i = tid; i < 16 * 129; i += 256) Hcur[i] = 0.0f;
    float creg[4][2];
#pragma unroll
    for (int r = 0; r < 4; r++) { creg[r][0] = 0.0f; creg[r][1] = 0.0f; }
    __syncthreads();

    for (int t = 0; t < TT; t++) {
        const float* zx = zx0 + (long)t * MM * 512;

        float acc[4][8];
#pragma unroll
        for (int r = 0; r < 4; r++)
#pragma unroll
            for (int q = 0; q < 8; q++) acc[r][q] = 0.0f;

        for (int k0 = 0; k0 < HID; k0 += BK) {
#pragma unroll
            for (int i = 0; i < 8; i++) {
                int idx = tid * 8 + i;
                int n  = idx >> 2;
                int kk = (idx & 3) * 4;
                float4 v = *(const float4*)(Whh + n * HID + k0 + kk);
                Ws[kk + 0][n] = v.x; Ws[kk + 1][n] = v.y;
                Ws[kk + 2][n] = v.z; Ws[kk + 3][n] = v.w;
            }
            __syncthreads();
#pragma unroll
            for (int k = 0; k < BK; k++) {
                float a[4], b[8];
#pragma unroll
                for (int r = 0; r < 4; r++) a[r] = Hcur[(rg * 4 + r) * 129 + k0 + k];
#pragma unroll
                for (int gidx = 0; gidx < 4; gidx++) {
                    b[gidx * 2]     = Ws[k][gidx * 128 + cg * 2];
                    b[gidx * 2 + 1] = Ws[k][gidx * 128 + cg * 2 + 1];
                }
#pragma unroll
                for (int r = 0; r < 4; r++)
#pragma unroll
                    for (int q = 0; q < 8; q++)
                        acc[r][q] = fmaf(a[r], b[q], acc[r][q]);
            }
            __syncthreads();
        }

#pragma unroll
        for (int r = 0; r < 4; r++) {
            int ml = rg * 4 + r;
            int m  = bm * 16 + ml;
#pragma unroll
            for (int q = 0; q < 2; q++) {
                int n = cg * 2 + q;
                float zi = acc[r][0 + q] + zx[m * 512 + n]       + bih[n]       + bhh[n];
                float zf = acc[r][2 + q] + zx[m * 512 + 128 + n] + bih[128 + n] + bhh[128 + n];
                float zg = acc[r][4 + q] + zx[m * 512 + 256 + n] + bih[256 + n] + bhh[256 + n];
                float zo = acc[r][6 + q] + zx[m * 512 + 384 + n] + bih[384 + n] + bhh[384 + n];
                float co = creg[r][q];
                float cn = sigf(zf) * co + sigf(zi) * tanhf(zg);
                float hn = sigf(zo) * tanhf(cn);
                creg[r][q] = cn;
                if (t == TT - 1) out[m * HID + n] = hn;
                else             Hcur[ml * 129 + n] = hn;
            }
        }
    }
}

// ---------------- host ----------------
extern "C" void kernel_launch(void* const* d_in, const int* in_sizes, int n_in,
                              void* d_out, int out_size)
{
    const float* x    = (const float*)d_in[0];
    const float* Ain  = (const float*)d_in[1];
    const float* Aout = (const float*)d_in[2];
    const float* Al   = (const float*)d_in[3];
    const void*  ips  = d_in[4];
    const void*  cur  = d_in[5];
    const float* W1   = (const float*)d_in[6];
    const float* b1   = (const float*)d_in[7];
    const float* W2   = (const float*)d_in[8];
    const float* b2   = (const float*)d_in[9];
    const float* Wg   = (const float*)d_in[10];
    const float* asrc = (const float*)d_in[11];
    const float* adst = (const float*)d_in[12];
    const float* Wih  = (const float*)d_in[13];
    const float* Whh  = (const float*)d_in[14];
    const float* bih  = (const float*)d_in[15];
    const float* bhh  = (const float*)d_in[16];
    float* out = (float*)d_out;

    float *XW, *FT, *G, *GAT, *SEQ, *ZX, *S, *D, *V, *V5, *RM, *RI, *WC;
    cudaGetSymbolAddress((void**)&XW,  g_XW);
    cudaGetSymbolAddress((void**)&FT,  g_FEAT);
    cudaGetSymbolAddress((void**)&G,   g_G);
    cudaGetSymbolAddress((void**)&GAT, g_GAT);
    cudaGetSymbolAddress((void**)&SEQ, g_SEQ);
    cudaGetSymbolAddress((void**)&ZX,  g_ZX);
    cudaGetSymbolAddress((void**)&S,   g_S);
    cudaGetSymbolAddress((void**)&D,   g_D);
    cudaGetSymbolAddress((void**)&V,   g_V);
    cudaGetSymbolAddress((void**)&V5,  g_V5);
    cudaGetSymbolAddress((void**)&RM,  g_RM);
    cudaGetSymbolAddress((void**)&RI,  g_RI);
    cudaGetSymbolAddress((void**)&WC,  g_WC);

    const long NN2 = (long)NN * NN;
    const long SNF = (long)NN * FEAT;

    // prep
    combine_w<<<64, 256>>>(W1, W2, WC);
    detect_kernel<<<1, 32>>>((const unsigned*)cur);

    // K1 (SIMT): XW = x @ [W1|W2]
    sgemm128<false><<<dim3(256, 2, 1), 256>>>(
        x, WC, XW, INDIM, INDIM, FEAT, FEAT, nullptr);

    // K2 (3xTF32 HMMA): feat[:,:128] = Ain @ xW1 + b1 ; feat[:,128:] = Aout @ xW2 + b2
    tf32_gemm<false, false><<<dim3(16, 1, TT), 256>>>(
        Ain, XW, FT, NN, NN, FEAT, FEAT, NN2, SNF, SNF, b1,
        nullptr, nullptr, nullptr, nullptr, nullptr, nullptr);
    tf32_gemm<false, false><<<dim3(16, 1, TT), 256>>>(
        Aout, XW + 128, FT + 128, NN, NN, FEAT, FEAT, NN2, SNF, SNF, b2,
        nullptr, nullptr, nullptr, nullptr, nullptr, nullptr);

    // K3 (SIMT): g = feat @ Wg
    sgemm128<false><<<dim3(256, 2, 1), 256>>>(
        FT, Wg, G, FEAT, FEAT, FEAT, FEAT, nullptr);

    // s, d
    sd_kernel<<<4096, 256>>>(G, asrc, adst, S, D);

    // column softmax factors V = exp(d), V5 = exp(0.2 d)
    vfac_kernel<<<128, 256>>>(D, V, V5);

    // softmax row stats (factored, no per-element exp)
    stats_kernel<<<dim3(NN, TT), 256>>>(Al, S, D, V, V5, RM, RI);

    // K5 (3xTF32 HMMA, factored fused-P): gat = softmax(e) @ g
    tf32_gemm<false, true><<<dim3(16, 2, TT), 256>>>(
        Al, G, GAT, NN, NN, FEAT, FEAT, NN2, SNF, SNF, nullptr,
        S, D, RM, RI, V, V5);

    // gather per (t, m)
    gather_kernel<<<4096, 256>>>(ips, cur, GAT, SEQ);

    // ZX (3xTF32 HMMA, TRANSB): seqs @ Wih^T
    tf32_gemm<true, false><<<dim3(256, 4, 1), 256>>>(
        SEQ, Wih, ZX, FEAT, FEAT, FEAT, 512, 0, 0, 0, nullptr,
        nullptr, nullptr, nullptr, nullptr, nullptr, nullptr);

    // fused 16-step LSTM
    lstm_fused<<<128, 256>>>(ZX, Whh, bih, bhh, out);
}